// round 3
// baseline (speedup 1.0000x reference)
#include <cuda_runtime.h>
#include <math.h>

#define N_TOT    87296
#define SEL_TOT  4256
#define SEL_PAD  4352
#define SEL_PAD2 4352
#define WW       136
#define JTILES   34
#define KSLAB    512
#define NSLAB    9
#define EQCAP    2048

// ---------------- scratch (device globals; no allocations) -----------------
__device__ float    g_key[N_TOT];
__device__ int      g_cls[N_TOT];
__device__ float    g_selKey[SEL_TOT];
__device__ int      g_selCls[SEL_TOT];
__device__ int      g_selTie[SEL_TOT];
__device__ float4   g_selBox[SEL_TOT];
__device__ float    g_srtScore[SEL_PAD];
__device__ int      g_srtCls[SEL_PAD];
__device__ int      g_srtValid[SEL_PAD];
__device__ float4   g_srtBox[SEL_PAD];
__device__ unsigned g_Mt[(size_t)WW * SEL_PAD2];   // column-major: Mt[w][j]
__device__ unsigned g_keep[2][WW];
__device__ unsigned g_keepOut[WW];
__device__ unsigned g_changeArr[16];
__device__ unsigned g_barCount = 0;
__device__ unsigned g_barGen   = 0;               // monotonic across replays

__device__ __forceinline__ unsigned fflip(float f) {
    unsigned u = __float_as_uint(f);
    return (u & 0x80000000u) ? ~u : (u | 0x80000000u);
}

// ---------------- 1. per-anchor class max (warp per anchor, float4) --------
__global__ void scoreKernel(const float* __restrict__ c0, const float* __restrict__ c1,
                            const float* __restrict__ c2, const float* __restrict__ c3,
                            const float* __restrict__ c4) {
    int warp = (blockIdx.x * blockDim.x + threadIdx.x) >> 5;
    int lane = threadIdx.x & 31;
    if (warp >= N_TOT) return;
    int off;
    const float* base;
    if      (warp < 65536) { off = 0;     base = c0; }
    else if (warp < 81920) { off = 65536; base = c1; }
    else if (warp < 86016) { off = 81920; base = c2; }
    else if (warp < 87040) { off = 86016; base = c3; }
    else                   { off = 87040; base = c4; }
    int a = warp - off;
    float v = -1e30f; int bi = 1 << 20;
    if (lane < 20) {
        const float4* p4 = reinterpret_cast<const float4*>(base + (size_t)a * 80);
        float4 q = p4[lane];
        int cb = lane * 4;
        v = q.x; bi = cb;
        if (q.y > v) { v = q.y; bi = cb + 1; }
        if (q.z > v) { v = q.z; bi = cb + 2; }
        if (q.w > v) { v = q.w; bi = cb + 3; }
    }
    for (int o = 16; o; o >>= 1) {
        float ov = __shfl_down_sync(0xffffffffu, v, o);
        int   oi = __shfl_down_sync(0xffffffffu, bi, o);
        if (ov > v || (ov == v && oi < bi)) { v = ov; bi = oi; }
    }
    if (lane == 0) {
        float ps = 1.0f / (1.0f + expf(-v));
        g_key[warp] = (ps > 0.05f) ? ps : -1.0f;
        g_cls[warp] = bi + 1;
    }
}

// ---------------- 2. per-level exact radix-select top-k + clip -------------
__global__ void selectKernel(const float* __restrict__ r0, const float* __restrict__ r1,
                             const float* __restrict__ r2, const float* __restrict__ r3,
                             const float* __restrict__ r4, const float* __restrict__ loc) {
    const int LNv[5]  = {65536, 16384, 4096, 1024, 256};
    const int OFFv[5] = {0, 65536, 81920, 86016, 87040};
    const int SOFF[5] = {0, 1000, 2000, 3000, 4000};
    const int LKv[5]  = {1000, 1000, 1000, 1000, 256};
    int lvl = blockIdx.x;
    int n = LNv[lvl], off = OFFv[lvl], k = LKv[lvl], sbase = SOFF[lvl];
    const float* key = g_key + off;
    const float* reg = (lvl == 0) ? r0 : (lvl == 1) ? r1 : (lvl == 2) ? r2 : (lvl == 3) ? r3 : r4;

    __shared__ unsigned hist[4][256];
    __shared__ unsigned sCur, sNeed;
    __shared__ int      eqBuf[EQCAP];
    __shared__ int      eqSel[EQCAP];
    int tid = threadIdx.x;
    int hgrp = (tid >> 5) & 3;
    if (tid == 0) { sCur = 0u; sNeed = (unsigned)k; }
    __syncthreads();

    for (int r = 3; r >= 0; r--) {
        for (int i = tid; i < 1024; i += blockDim.x) hist[i >> 8][i & 255] = 0u;
        __syncthreads();
        unsigned cur = sCur;
        unsigned hm  = (r == 3) ? 0u : (0xFFFFFFFFu << ((r + 1) * 8));
        for (int i = tid; i < n; i += blockDim.x) {
            unsigned u = fflip(key[i]);
            if ((u & hm) == cur) atomicAdd(&hist[hgrp][(u >> (r * 8)) & 255u], 1u);
        }
        __syncthreads();
        if (tid == 0) {
            unsigned need = sNeed, acc = 0; int b = 0;
            for (int bb = 255; bb >= 0; bb--) {
                unsigned h = hist[0][bb] + hist[1][bb] + hist[2][bb] + hist[3][bb];
                if (acc + h >= need) { b = bb; break; }
                acc += h;
            }
            sNeed = need - acc;
            sCur  = cur | ((unsigned)b << (r * 8));
        }
        __syncthreads();
    }
    unsigned pivot = sCur;
    int need = (int)sNeed;
    int G = k - need;
    __shared__ int cg, ce;
    if (tid == 0) { cg = 0; ce = 0; }
    __syncthreads();

    float l0 = loc[0], l1 = loc[1], l2 = loc[2], l3 = loc[3];
    for (int i = tid; i < n; i += blockDim.x) {
        float kf = key[i];
        unsigned u = fflip(kf);
        int slot = -1;
        if (u > pivot) slot = sbase + atomicAdd(&cg, 1);
        else if (u == pivot) {
            int t = atomicAdd(&ce, 1);
            if (t < EQCAP) eqBuf[t] = i;
        }
        if (slot >= 0) {
            g_selKey[slot] = kf;
            g_selCls[slot] = g_cls[off + i];
            g_selTie[slot] = (lvl << 17) | i;
            float b0 = reg[(size_t)i * 4 + 0], b1 = reg[(size_t)i * 4 + 1];
            float b2 = reg[(size_t)i * 4 + 2], b3 = reg[(size_t)i * 4 + 3];
            g_selBox[slot] = make_float4(fmaxf(b0, l0), fmaxf(b1, l1),
                                         fminf(b2, l2), fminf(b3, l3));
        }
    }
    __syncthreads();
    // `need` smallest indices among equal-to-pivot (matches top_k tie order)
    if (tid == 0) {
        int m = ce; if (m > EQCAP) m = EQCAP;
        for (int t = 0; t < need; t++) {
            int best = -1, bestv = 0x7FFFFFFF;
            for (int q = 0; q < m; q++) {
                int v = eqBuf[q];
                if (v >= 0 && v < bestv) { bestv = v; best = q; }
            }
            eqSel[t] = bestv;
            if (best >= 0) eqBuf[best] = -1;
        }
    }
    __syncthreads();
    if (tid < need) {
        int i = eqSel[tid];
        int slot = sbase + G + tid;
        g_selKey[slot] = key[i];
        g_selCls[slot] = g_cls[off + i];
        g_selTie[slot] = (lvl << 17) | i;
        float b0 = reg[(size_t)i * 4 + 0], b1 = reg[(size_t)i * 4 + 1];
        float b2 = reg[(size_t)i * 4 + 2], b3 = reg[(size_t)i * 4 + 3];
        g_selBox[slot] = make_float4(fmaxf(b0, l0), fmaxf(b1, l1),
                                     fminf(b2, l2), fminf(b3, l3));
    }
}

// ---------------- 3. deterministic rank-sort of 4256 elements --------------
__global__ void rankKernel() {
    __shared__ unsigned long long sk[SEL_TOT];
    int tid = threadIdx.x;
    int gt  = blockIdx.x * blockDim.x + tid;
    for (int i = tid; i < SEL_TOT; i += blockDim.x) {
        float kf = g_selKey[i];
        float ss = (kf > 0.0f) ? kf : 0.0f;
        unsigned tie = (unsigned)g_selTie[i];
        sk[i] = ((unsigned long long)fflip(ss) << 20) |
                (unsigned long long)(0xFFFFFu - tie);
    }
    __syncthreads();
    if (gt < SEL_TOT) {
        unsigned long long mine = sk[gt];
        int rank = 0;
        #pragma unroll 8
        for (int i = 0; i < SEL_TOT; i++) rank += (sk[i] > mine) ? 1 : 0;
        float kf = g_selKey[gt];
        g_srtScore[rank] = (kf > 0.0f) ? kf : 0.0f;
        g_srtValid[rank] = (kf > 0.0f) ? 1 : 0;
        g_srtCls[rank]   = g_selCls[gt];
        g_srtBox[rank]   = g_selBox[gt];
    }
    if (gt < 16) g_changeArr[gt] = 0u;
}

// ------- 4. suppression bitmask, column-major (bit k of word w, col j) ------
__global__ void matrixKernel() {
    int jbase = blockIdx.x * 128;
    int kbase = blockIdx.y * KSLAB;
    if (kbase >= jbase + 128) return;                // entire slab above diagonal
    __shared__ float4 kb[KSLAB];
    int tid = threadIdx.x;
    for (int t = tid; t < KSLAB; t += 128) {
        int kk = kbase + t;
        kb[t] = (kk < SEL_TOT) ? g_srtBox[kk] : make_float4(0.f, 0.f, 0.f, 0.f);
    }
    __syncthreads();
    int j = jbase + tid;
    if (j >= SEL_TOT) return;
    float4 bj = g_srtBox[j];
    float aj = fmaxf(bj.z - bj.x, 0.f) * fmaxf(bj.w - bj.y, 0.f);
    int w0 = kbase >> 5;
    for (int wi = 0; wi < KSLAB / 32; wi++) {
        unsigned word = 0u;
        int tb = wi * 32;
        #pragma unroll
        for (int t = 0; t < 32; t++) {
            int k = kbase + tb + t;
            float4 bk = kb[tb + t];
            float ak = fmaxf(bk.z - bk.x, 0.f) * fmaxf(bk.w - bk.y, 0.f);
            float iy1 = fmaxf(bk.x, bj.x), ix1 = fmaxf(bk.y, bj.y);
            float iy2 = fminf(bk.z, bj.z), ix2 = fminf(bk.w, bj.w);
            float inter = fmaxf(iy2 - iy1, 0.f) * fmaxf(ix2 - ix1, 0.f);
            float uni = aj + ak - inter;
            bool bit = (k < j) && (inter > 0.5f * fmaxf(uni, 1e-9f));
            if (bit) word |= (1u << t);
        }
        g_Mt[(size_t)(w0 + wi) * SEL_PAD2 + j] = word;
    }
}

// -------- 5. all 16 Jacobi iterations in ONE kernel (grid barrier) ---------
__device__ __forceinline__ void gridBarrier(unsigned nb) {
    __threadfence();
    __syncthreads();
    if (threadIdx.x == 0) {
        unsigned my = atomicAdd(&g_barGen, 0u);
        if (atomicAdd(&g_barCount, 1u) == nb - 1u) {
            atomicExch(&g_barCount, 0u);
            __threadfence();
            atomicAdd(&g_barGen, 1u);
        } else {
            while (atomicAdd(&g_barGen, 0u) == my) __nanosleep(64);
        }
    }
    __syncthreads();
}

__global__ void nmsKernel() {
    __shared__ unsigned sK[WW];
    int tid = threadIdx.x;
    int j = blockIdx.x * 128 + tid;
    int lane = tid & 31;
    int wj = j >> 5;
    int wtop = (j > 0 && j < SEL_TOT) ? (((j - 1) >> 5) + 1) : 0;
    const unsigned* col = g_Mt + j;                // column j, stride SEL_PAD2
    unsigned lastBal = 0xFFFFFFFFu;

    for (int t = 0; t < 16; t++) {
        // load keep_t (t==0: all ones, implicit)
        if (t == 0) {
            for (int w = tid; w < WW; w += 128) sK[w] = 0xFFFFFFFFu;
        } else {
            const unsigned* src = g_keep[(t - 1) & 1];
            for (int w = tid; w < WW; w += 128) sK[w] = __ldcg(&src[w]);
        }
        __syncthreads();
        unsigned acc = 0u;
        #pragma unroll 4
        for (int w = 0; w < wtop; w++)
            acc |= col[(size_t)w * SEL_PAD2] & sK[w];
        bool keepNew = (acc == 0u);
        unsigned bal = __ballot_sync(0xffffffffu, keepNew);
        unsigned oldw = sK[wj];
        if (lane == 0) {
            __stcg(&g_keep[t & 1][wj], bal);
            if (bal != oldw) atomicOr(&g_changeArr[t], 1u);
        }
        lastBal = bal;
        gridBarrier(JTILES);                        // publishes keep_{t+1} + change flag
        unsigned chg = __ldcg(&g_changeArr[t]);     // uniform across grid
        __syncthreads();
        if (chg == 0u) break;                       // fixed point: all remaining identical
    }
    if (lane == 0) __stcg(&g_keepOut[wj], lastBal); // each block owns its 4 words
}

// ---------------- 6. final top-100 + rescale + write -----------------------
__global__ void finalKernel(float* __restrict__ out, const float* __restrict__ loc,
                            int out_size) {
    __shared__ unsigned char kept[SEL_TOT];
    __shared__ int sel[100];
    int tid = threadIdx.x;
    for (int j = tid; j < SEL_TOT; j += blockDim.x) {
        unsigned w = g_keepOut[j >> 5];
        kept[j] = (unsigned char)(((w >> (j & 31)) & 1u) && g_srtValid[j]);
    }
    __syncthreads();
    if (tid == 0) {
        int cnt = 0;
        for (int j = 0; j < SEL_TOT && cnt < 100; j++) if (kept[j])  sel[cnt++] = j;
        for (int j = 0; j < SEL_TOT && cnt < 100; j++) if (!kept[j]) sel[cnt++] = j;
    }
    __syncthreads();
    if (tid < 100) {
        int j = sel[tid];
        float vy1 = loc[0], vx1 = loc[1], vy2 = loc[2], vx2 = loc[3];
        float oh = loc[4], ow = loc[5];
        float sy = oh / fmaxf(vy2 - vy1, 1e-6f);
        float sx = ow / fmaxf(vx2 - vx1, 1e-6f);
        float4 b = g_srtBox[j];
        if (tid * 4 + 3 < out_size) {
            out[tid * 4 + 0] = (b.x - vy1) * sy;
            out[tid * 4 + 1] = (b.y - vx1) * sx;
            out[tid * 4 + 2] = (b.z - vy1) * sy;
            out[tid * 4 + 3] = (b.w - vx1) * sx;
        }
        if (400 + tid < out_size) out[400 + tid] = (float)g_srtCls[j];
        if (500 + tid < out_size) out[500 + tid] = kept[j] ? g_srtScore[j] : 0.0f;
    }
}

// ---------------- host launcher --------------------------------------------
extern "C" void kernel_launch(void* const* d_in, const int* in_sizes, int n_in,
                              void* d_out, int out_size) {
    const float *cls[5] = {0, 0, 0, 0, 0};
    const float *reg[5] = {0, 0, 0, 0, 0};
    const float *loc = 0;
    for (int i = 0; i < n_in; i++) {
        switch (in_sizes[i]) {
            case 5242880: cls[0] = (const float*)d_in[i]; break;
            case 1310720: cls[1] = (const float*)d_in[i]; break;
            case 327680:  cls[2] = (const float*)d_in[i]; break;
            case 81920:   cls[3] = (const float*)d_in[i]; break;
            case 20480:   cls[4] = (const float*)d_in[i]; break;
            case 262144:  reg[0] = (const float*)d_in[i]; break;
            case 65536:   reg[1] = (const float*)d_in[i]; break;
            case 16384:   reg[2] = (const float*)d_in[i]; break;
            case 4096:    reg[3] = (const float*)d_in[i]; break;
            case 1024:    reg[4] = (const float*)d_in[i]; break;
            case 6:       loc    = (const float*)d_in[i]; break;
            default: break;
        }
    }
    int blocks = (N_TOT * 32 + 255) / 256;
    scoreKernel<<<blocks, 256>>>(cls[0], cls[1], cls[2], cls[3], cls[4]);
    selectKernel<<<5, 1024>>>(reg[0], reg[1], reg[2], reg[3], reg[4], loc);
    rankKernel<<<JTILES, 128>>>();
    dim3 mg(JTILES, NSLAB);
    matrixKernel<<<mg, 128>>>();
    nmsKernel<<<JTILES, 128>>>();
    finalKernel<<<1, 128>>>((float*)d_out, loc, out_size);
}

// round 5
// speedup vs baseline: 1.0386x; 1.0386x over previous
#include <cuda_runtime.h>
#include <math.h>

#define N_TOT    87296
#define SEL_TOT  4256
#define SEL_PAD  4352
#define SEL_PAD2 4352
#define WW       136
#define JTILES   34
#define KSLAB    256
#define NSLAB    17
#define EQCAP    2048

// ---------------- scratch (device globals; no allocations) -----------------
__device__ float    g_key[N_TOT];
__device__ int      g_cls[N_TOT];
__device__ float    g_selKey[SEL_TOT];
__device__ int      g_selCls[SEL_TOT];
__device__ int      g_selTie[SEL_TOT];
__device__ float4   g_selBox[SEL_TOT];
__device__ float    g_srtScore[SEL_PAD];
__device__ int      g_srtCls[SEL_PAD];
__device__ int      g_srtValid[SEL_PAD];
__device__ float4   g_srtBox[SEL_PAD];
__device__ unsigned long long g_bufA[N_TOT];
__device__ unsigned long long g_bufB[N_TOT];
__device__ unsigned g_Mt[(size_t)WW * SEL_PAD2];   // column-major: Mt[w][j]
__device__ unsigned g_keep[2][WW];
__device__ unsigned g_keepOut[WW];
__device__ unsigned g_changeArr[16];
__device__ unsigned g_barCount = 0;
__device__ unsigned g_barGen   = 0;               // monotonic across replays

__device__ __forceinline__ unsigned fflip(float f) {
    unsigned u = __float_as_uint(f);
    return (u & 0x80000000u) ? ~u : (u | 0x80000000u);
}

// ---------------- 1. per-anchor class max (warp per anchor, float4) --------
__global__ void scoreKernel(const float* __restrict__ c0, const float* __restrict__ c1,
                            const float* __restrict__ c2, const float* __restrict__ c3,
                            const float* __restrict__ c4) {
    int warp = (blockIdx.x * blockDim.x + threadIdx.x) >> 5;
    int lane = threadIdx.x & 31;
    if (warp >= N_TOT) return;
    int off;
    const float* base;
    if      (warp < 65536) { off = 0;     base = c0; }
    else if (warp < 81920) { off = 65536; base = c1; }
    else if (warp < 86016) { off = 81920; base = c2; }
    else if (warp < 87040) { off = 86016; base = c3; }
    else                   { off = 87040; base = c4; }
    int a = warp - off;
    float v = -1e30f; int bi = 1 << 20;
    if (lane < 20) {
        const float4* p4 = reinterpret_cast<const float4*>(base + (size_t)a * 80);
        float4 q = p4[lane];
        int cb = lane * 4;
        v = q.x; bi = cb;
        if (q.y > v) { v = q.y; bi = cb + 1; }
        if (q.z > v) { v = q.z; bi = cb + 2; }
        if (q.w > v) { v = q.w; bi = cb + 3; }
    }
    for (int o = 16; o; o >>= 1) {
        float ov = __shfl_down_sync(0xffffffffu, v, o);
        int   oi = __shfl_down_sync(0xffffffffu, bi, o);
        if (ov > v || (ov == v && oi < bi)) { v = ov; bi = oi; }
    }
    if (lane == 0) {
        float ps = 1.0f / (1.0f + expf(-v));
        g_key[warp] = (ps > 0.05f) ? ps : -1.0f;
        g_cls[warp] = bi + 1;
    }
}

// ---------------- 2. per-level radix-select: 2 full passes + buffer --------
__device__ __forceinline__ void writeSel(int slot, float kf, int gidx, int lvl, int i,
                                         const float* __restrict__ reg,
                                         float l0, float l1, float l2, float l3) {
    g_selKey[slot] = kf;
    g_selCls[slot] = g_cls[gidx];
    g_selTie[slot] = (lvl << 17) | i;
    float b0 = reg[(size_t)i * 4 + 0], b1 = reg[(size_t)i * 4 + 1];
    float b2 = reg[(size_t)i * 4 + 2], b3 = reg[(size_t)i * 4 + 3];
    g_selBox[slot] = make_float4(fmaxf(b0, l0), fmaxf(b1, l1),
                                 fminf(b2, l2), fminf(b3, l3));
}

__global__ void selectKernel(const float* __restrict__ r0, const float* __restrict__ r1,
                             const float* __restrict__ r2, const float* __restrict__ r3,
                             const float* __restrict__ r4, const float* __restrict__ loc) {
    const int LNv[5]  = {65536, 16384, 4096, 1024, 256};
    const int OFFv[5] = {0, 65536, 81920, 86016, 87040};
    const int SOFF[5] = {0, 1000, 2000, 3000, 4000};
    const int LKv[5]  = {1000, 1000, 1000, 1000, 256};
    int lvl = blockIdx.x;
    int n = LNv[lvl], off = OFFv[lvl], k = LKv[lvl], sbase = SOFF[lvl];
    const float* key = g_key + off;
    const float* reg = (lvl == 0) ? r0 : (lvl == 1) ? r1 : (lvl == 2) ? r2 : (lvl == 3) ? r3 : r4;

    __shared__ unsigned hist[4][256];
    __shared__ unsigned sCur;
    __shared__ int sNeed, cg, cntIn, cntOut;
    __shared__ int eqIdx[EQCAP];
    int tid = threadIdx.x;
    int hgrp = (tid >> 5) & 3;
    float l0 = loc[0], l1 = loc[1], l2 = loc[2], l3 = loc[3];

    // ---- pass 1: top-byte histogram (full read) ----
    for (int i = tid; i < 1024; i += blockDim.x) hist[i >> 8][i & 255] = 0u;
    __syncthreads();
    for (int i = tid; i < n; i += blockDim.x)
        atomicAdd(&hist[hgrp][fflip(key[i]) >> 24], 1u);
    __syncthreads();
    if (tid == 0) {
        cg = 0; cntIn = 0;
        unsigned acc = 0; int b = 0;
        for (int bb = 255; bb >= 0; bb--) {
            unsigned h = hist[0][bb] + hist[1][bb] + hist[2][bb] + hist[3][bb];
            if (acc + h >= (unsigned)k) { b = bb; break; }
            acc += h;
        }
        sCur = (unsigned)b << 24;
        sNeed = k - (int)acc;
    }
    __syncthreads();
    unsigned b3 = sCur >> 24;

    // ---- pass 2: winners direct, pivot-byte ties -> buffer ----
    for (int i = tid; i < n; i += blockDim.x) {
        float kf = key[i];
        unsigned u = fflip(kf);
        unsigned top = u >> 24;
        if (top > b3) {
            int slot = sbase + atomicAdd(&cg, 1);
            writeSel(slot, kf, off + i, lvl, i, reg, l0, l1, l2, l3);
        } else if (top == b3) {
            int t = atomicAdd(&cntIn, 1);
            g_bufA[off + t] = ((unsigned long long)u << 32) | (unsigned)i;
        }
    }
    __syncthreads();

    unsigned long long* bin  = g_bufA + off;
    unsigned long long* bout = g_bufB + off;
    for (int r = 2; r >= 0; r--) {
        for (int i = tid; i < 1024; i += blockDim.x) hist[i >> 8][i & 255] = 0u;
        if (tid == 0) cntOut = 0;
        __syncthreads();
        int m = cntIn;
        for (int i = tid; i < m; i += blockDim.x) {
            unsigned u = (unsigned)(bin[i] >> 32);
            atomicAdd(&hist[hgrp][(u >> (r * 8)) & 255u], 1u);
        }
        __syncthreads();
        if (tid == 0) {
            int needv = sNeed;
            unsigned acc = 0; int b = 0;
            for (int bb = 255; bb >= 0; bb--) {
                unsigned h = hist[0][bb] + hist[1][bb] + hist[2][bb] + hist[3][bb];
                if (acc + h >= (unsigned)needv) { b = bb; break; }
                acc += h;
            }
            sNeed = needv - (int)acc;
            sCur  = sCur | ((unsigned)b << (r * 8));
        }
        __syncthreads();
        unsigned bsel = (sCur >> (r * 8)) & 255u;
        for (int i = tid; i < m; i += blockDim.x) {
            unsigned long long e = bin[i];
            unsigned u = (unsigned)(e >> 32);
            unsigned by = (u >> (r * 8)) & 255u;
            if (by > bsel) {
                int idx2 = (int)(e & 0xFFFFFFFFull);
                int slot = sbase + atomicAdd(&cg, 1);
                writeSel(slot, key[idx2], off + idx2, lvl, idx2, reg, l0, l1, l2, l3);
            } else if (by == bsel) {
                int t = atomicAdd(&cntOut, 1);
                bout[t] = e;
            }
        }
        __syncthreads();
        if (tid == 0) cntIn = cntOut;
        unsigned long long* tmp = bin; bin = bout; bout = tmp;
        __syncthreads();
    }

    // ---- equal-to-pivot: take `need` smallest indices (top_k tie order) ----
    int ceF = cntIn; if (ceF > EQCAP) ceF = EQCAP;
    int needF = sNeed;
    for (int i = tid; i < ceF; i += blockDim.x)
        eqIdx[i] = (int)(bin[i] & 0xFFFFFFFFull);
    __syncthreads();
    if (tid == 0) {
        // partial selection sort: first needF entries ascending
        for (int t = 0; t < needF; t++) {
            int best = t;
            for (int q = t + 1; q < ceF; q++)
                if (eqIdx[q] < eqIdx[best]) best = q;
            int tmp = eqIdx[t]; eqIdx[t] = eqIdx[best]; eqIdx[best] = tmp;
        }
    }
    __syncthreads();
    int G = cg;                                    // winners so far = k - needF
    if (tid < needF) {
        int i2 = eqIdx[tid];
        writeSel(sbase + G + tid, key[i2], off + i2, lvl, i2, reg, l0, l1, l2, l3);
    }
}

// ---------------- 3. deterministic rank-sort of 4256 elements --------------
__global__ void rankKernel() {
    __shared__ unsigned long long sk[SEL_TOT];
    int tid = threadIdx.x;
    int gt  = blockIdx.x * blockDim.x + tid;
    for (int i = tid; i < SEL_TOT; i += blockDim.x) {
        float kf = g_selKey[i];
        float ss = (kf > 0.0f) ? kf : 0.0f;
        unsigned tie = (unsigned)g_selTie[i];
        sk[i] = ((unsigned long long)fflip(ss) << 20) |
                (unsigned long long)(0xFFFFFu - tie);
    }
    __syncthreads();
    if (gt < SEL_TOT) {
        unsigned long long mine = sk[gt];
        int rank = 0;
        #pragma unroll 8
        for (int i = 0; i < SEL_TOT; i++) rank += (sk[i] > mine) ? 1 : 0;
        float kf = g_selKey[gt];
        g_srtScore[rank] = (kf > 0.0f) ? kf : 0.0f;
        g_srtValid[rank] = (kf > 0.0f) ? 1 : 0;
        g_srtCls[rank]   = g_selCls[gt];
        g_srtBox[rank]   = g_selBox[gt];
    }
    if (gt < 16) g_changeArr[gt] = 0u;
}

// ------- 4. suppression bitmask, column-major (bit k of word w, col j) ------
__global__ void matrixKernel() {
    int jbase = blockIdx.x * 128;
    int kbase = blockIdx.y * KSLAB;
    if (kbase >= jbase + 128) return;                // entire slab above diagonal
    __shared__ float4 kb[KSLAB];
    __shared__ float  ka[KSLAB];
    int tid = threadIdx.x;
    for (int t = tid; t < KSLAB; t += 128) {
        int kk = kbase + t;
        float4 b = (kk < SEL_TOT) ? g_srtBox[kk] : make_float4(0.f, 0.f, 0.f, 0.f);
        kb[t] = b;
        ka[t] = fmaxf(b.z - b.x, 0.f) * fmaxf(b.w - b.y, 0.f);
    }
    __syncthreads();
    int j = jbase + tid;
    if (j >= SEL_TOT) return;
    float4 bj = g_srtBox[j];
    float aj = fmaxf(bj.z - bj.x, 0.f) * fmaxf(bj.w - bj.y, 0.f);
    int w0 = kbase >> 5;
    for (int wi = 0; wi < KSLAB / 32; wi++) {
        unsigned word = 0u;
        int tb = wi * 32;
        if (kbase + tb < j) {
            #pragma unroll
            for (int t = 0; t < 32; t++) {
                int k = kbase + tb + t;
                float4 bk = kb[tb + t];
                float iy1 = fmaxf(bk.x, bj.x), ix1 = fmaxf(bk.y, bj.y);
                float iy2 = fminf(bk.z, bj.z), ix2 = fminf(bk.w, bj.w);
                float inter = fmaxf(iy2 - iy1, 0.f) * fmaxf(ix2 - ix1, 0.f);
                float uni = aj + ka[tb + t] - inter;
                bool bit = (k < j) && (inter > 0.5f * fmaxf(uni, 1e-9f));
                if (bit) word |= (1u << t);
            }
        }
        g_Mt[(size_t)(w0 + wi) * SEL_PAD2 + j] = word;
    }
}

// -------- 5. all 16 Jacobi iterations in ONE kernel (grid barrier) ---------
__device__ __forceinline__ void gridBarrier(unsigned nb) {
    __threadfence();
    __syncthreads();
    if (threadIdx.x == 0) {
        unsigned my = atomicAdd(&g_barGen, 0u);
        if (atomicAdd(&g_barCount, 1u) == nb - 1u) {
            atomicExch(&g_barCount, 0u);
            __threadfence();
            atomicAdd(&g_barGen, 1u);
        } else {
            while (atomicAdd(&g_barGen, 0u) == my) __nanosleep(64);
        }
    }
    __syncthreads();
}

__global__ void nmsKernel() {
    __shared__ unsigned sK[WW];
    int tid = threadIdx.x;
    int j = blockIdx.x * 128 + tid;
    int lane = tid & 31;
    int wj = j >> 5;
    int wtop = (j > 0 && j < SEL_TOT) ? (((j - 1) >> 5) + 1) : 0;
    const unsigned* col = g_Mt + j;
    unsigned lastBal = 0xFFFFFFFFu;

    for (int t = 0; t < 16; t++) {
        if (t == 0) {
            for (int w = tid; w < WW; w += 128) sK[w] = 0xFFFFFFFFu;
        } else {
            const unsigned* src = g_keep[(t - 1) & 1];
            for (int w = tid; w < WW; w += 128) sK[w] = __ldcg(&src[w]);
        }
        __syncthreads();
        unsigned acc = 0u;
        #pragma unroll 4
        for (int w = 0; w < wtop; w++)
            acc |= col[(size_t)w * SEL_PAD2] & sK[w];
        bool keepNew = (acc == 0u);
        unsigned bal = __ballot_sync(0xffffffffu, keepNew);
        unsigned oldw = sK[wj];
        if (lane == 0) {
            __stcg(&g_keep[t & 1][wj], bal);
            if (bal != oldw) atomicOr(&g_changeArr[t], 1u);
        }
        lastBal = bal;
        gridBarrier(JTILES);
        unsigned chg = __ldcg(&g_changeArr[t]);
        __syncthreads();
        if (chg == 0u) break;
    }
    if (lane == 0) __stcg(&g_keepOut[wj], lastBal);
}

// ------------- 6. final top-100 via parallel bitmask compaction ------------
__global__ void finalKernel(float* __restrict__ out, const float* __restrict__ loc,
                            int out_size) {
    __shared__ unsigned kw[WW];
    __shared__ int wpfx[WW + 1];
    __shared__ int sel[100];
    __shared__ int sKtot;
    int tid = threadIdx.x;

    for (int w = tid; w < WW; w += blockDim.x) {
        unsigned vb = 0u;
        int base = w * 32;
        #pragma unroll 4
        for (int b = 0; b < 32; b++) {
            int j = base + b;
            if (j < SEL_TOT && g_srtValid[j]) vb |= (1u << b);
        }
        kw[w] = g_keepOut[w] & vb;
    }
    __syncthreads();
    if (tid == 0) {
        int acc = 0;
        for (int w = 0; w < WW; w++) { wpfx[w] = acc; acc += __popc(kw[w]); }
        wpfx[WW] = acc;
        sKtot = acc;
    }
    __syncthreads();
    int Ktot = sKtot;
    for (int j = tid; j < SEL_TOT; j += blockDim.x) {
        int w = j >> 5, b = j & 31;
        unsigned below = (b == 0) ? 0u : (kw[w] & (0xFFFFFFFFu >> (32 - b)));
        int kr = wpfx[w] + __popc(below);
        bool kp = (kw[w] >> b) & 1u;
        if (kp) {
            if (kr < 100) sel[kr] = j;
        } else if (Ktot < 100) {
            int pos = Ktot + (j - kr);
            if (pos < 100) sel[pos] = j;
        }
    }
    __syncthreads();
    if (tid < 100) {
        int j = sel[tid];
        int w = j >> 5, b = j & 31;
        bool kp = (kw[w] >> b) & 1u;
        float vy1 = loc[0], vx1 = loc[1], vy2 = loc[2], vx2 = loc[3];
        float oh = loc[4], ow = loc[5];
        float sy = oh / fmaxf(vy2 - vy1, 1e-6f);
        float sx = ow / fmaxf(vx2 - vx1, 1e-6f);
        float4 bx = g_srtBox[j];
        if (tid * 4 + 3 < out_size) {
            out[tid * 4 + 0] = (bx.x - vy1) * sy;
            out[tid * 4 + 1] = (bx.y - vx1) * sx;
            out[tid * 4 + 2] = (bx.z - vy1) * sy;
            out[tid * 4 + 3] = (bx.w - vx1) * sx;
        }
        if (400 + tid < out_size) out[400 + tid] = (float)g_srtCls[j];
        if (500 + tid < out_size) out[500 + tid] = kp ? g_srtScore[j] : 0.0f;
    }
}

// ---------------- host launcher --------------------------------------------
extern "C" void kernel_launch(void* const* d_in, const int* in_sizes, int n_in,
                              void* d_out, int out_size) {
    const float *cls[5] = {0, 0, 0, 0, 0};
    const float *reg[5] = {0, 0, 0, 0, 0};
    const float *loc = 0;
    for (int i = 0; i < n_in; i++) {
        switch (in_sizes[i]) {
            case 5242880: cls[0] = (const float*)d_in[i]; break;
            case 1310720: cls[1] = (const float*)d_in[i]; break;
            case 327680:  cls[2] = (const float*)d_in[i]; break;
            case 81920:   cls[3] = (const float*)d_in[i]; break;
            case 20480:   cls[4] = (const float*)d_in[i]; break;
            case 262144:  reg[0] = (const float*)d_in[i]; break;
            case 65536:   reg[1] = (const float*)d_in[i]; break;
            case 16384:   reg[2] = (const float*)d_in[i]; break;
            case 4096:    reg[3] = (const float*)d_in[i]; break;
            case 1024:    reg[4] = (const float*)d_in[i]; break;
            case 6:       loc    = (const float*)d_in[i]; break;
            default: break;
        }
    }
    int blocks = (N_TOT * 32 + 255) / 256;
    scoreKernel<<<blocks, 256>>>(cls[0], cls[1], cls[2], cls[3], cls[4]);
    selectKernel<<<5, 1024>>>(reg[0], reg[1], reg[2], reg[3], reg[4], loc);
    rankKernel<<<JTILES, 128>>>();
    dim3 mg(JTILES, NSLAB);
    matrixKernel<<<mg, 128>>>();
    nmsKernel<<<JTILES, 128>>>();
    finalKernel<<<1, 256>>>((float*)d_out, loc, out_size);
}

// round 6
// speedup vs baseline: 1.4475x; 1.3937x over previous
#include <cuda_runtime.h>
#include <math.h>

#define N_TOT    87296
#define SEL_TOT  4256
#define SEL_PAD  4352
#define SEL_PAD2 4352
#define WW       136
#define JTILES   34
#define KSLAB    256
#define NSLAB    17
#define EQCAP    2048
#define HBINS    8192

// ---------------- scratch (device globals; no allocations) -----------------
__device__ float    g_key[N_TOT];
__device__ int      g_cls[N_TOT];
__device__ float    g_selKey[SEL_TOT];
__device__ int      g_selCls[SEL_TOT];
__device__ int      g_selTie[SEL_TOT];
__device__ float4   g_selBox[SEL_TOT];
__device__ float    g_srtScore[SEL_PAD];
__device__ int      g_srtCls[SEL_PAD];
__device__ int      g_srtValid[SEL_PAD];
__device__ float4   g_srtBox[SEL_PAD];
__device__ unsigned long long g_bufA[N_TOT];
__device__ unsigned long long g_bufB[N_TOT];
__device__ unsigned g_hist[5 * HBINS];
__device__ unsigned g_b13[5];
__device__ int      g_need[5];
__device__ int      g_cg[5];
__device__ int      g_cntTie[5];
__device__ unsigned g_Mt[(size_t)WW * SEL_PAD2];   // column-major: Mt[w][j]
__device__ unsigned g_keep[2][WW];
__device__ unsigned g_keepOut[WW];
__device__ unsigned g_changeArr[16];
__device__ unsigned g_barCount = 0;
__device__ unsigned g_barGen   = 0;               // monotonic across replays

__device__ __forceinline__ unsigned fflip(float f) {
    unsigned u = __float_as_uint(f);
    return (u & 0x80000000u) ? ~u : (u | 0x80000000u);
}

__device__ __forceinline__ void blk2lvl(int b, int& lvl, int& start, int& nk) {
    if      (b < 64) { lvl = 0; start = b * 1024;                 nk = 1024; }
    else if (b < 80) { lvl = 1; start = 65536 + (b - 64) * 1024;  nk = 1024; }
    else if (b < 84) { lvl = 2; start = 81920 + (b - 80) * 1024;  nk = 1024; }
    else if (b < 85) { lvl = 3; start = 86016;                    nk = 1024; }
    else             { lvl = 4; start = 87040;                    nk = 256;  }
}

__constant__ int c_OFF[5]  = {0, 65536, 81920, 86016, 87040};
__constant__ int c_SOFF[5] = {0, 1000, 2000, 3000, 4000};
__constant__ int c_K[5]    = {1000, 1000, 1000, 1000, 256};

// ---------------- 1. per-anchor class max (warp per anchor, float4) --------
__global__ void scoreKernel(const float* __restrict__ c0, const float* __restrict__ c1,
                            const float* __restrict__ c2, const float* __restrict__ c3,
                            const float* __restrict__ c4) {
    int gid = blockIdx.x * blockDim.x + threadIdx.x;
    if (gid < 5 * HBINS) g_hist[gid] = 0u;          // zero hist for this replay
    int warp = gid >> 5;
    int lane = threadIdx.x & 31;
    if (warp >= N_TOT) return;
    int off;
    const float* base;
    if      (warp < 65536) { off = 0;     base = c0; }
    else if (warp < 81920) { off = 65536; base = c1; }
    else if (warp < 86016) { off = 81920; base = c2; }
    else if (warp < 87040) { off = 86016; base = c3; }
    else                   { off = 87040; base = c4; }
    int a = warp - off;
    float v = -1e30f; int bi = 1 << 20;
    if (lane < 20) {
        const float4* p4 = reinterpret_cast<const float4*>(base + (size_t)a * 80);
        float4 q = p4[lane];
        int cb = lane * 4;
        v = q.x; bi = cb;
        if (q.y > v) { v = q.y; bi = cb + 1; }
        if (q.z > v) { v = q.z; bi = cb + 2; }
        if (q.w > v) { v = q.w; bi = cb + 3; }
    }
    for (int o = 16; o; o >>= 1) {
        float ov = __shfl_down_sync(0xffffffffu, v, o);
        int   oi = __shfl_down_sync(0xffffffffu, bi, o);
        if (ov > v || (ov == v && oi < bi)) { v = ov; bi = oi; }
    }
    if (lane == 0) {
        float ps = 1.0f / (1.0f + expf(-v));
        g_key[warp] = (ps > 0.05f) ? ps : -1.0f;
        g_cls[warp] = bi + 1;
    }
}

// ---------------- 2a. parallel 13-bit histogram (86 blocks) ----------------
__global__ void histKernel() {
    __shared__ unsigned h[HBINS];
    int tid = threadIdx.x;
    for (int i = tid; i < HBINS; i += 256) h[i] = 0u;
    __syncthreads();
    int lvl, start, nk; blk2lvl(blockIdx.x, lvl, start, nk);
    int lane = tid & 31;
    for (int it = 0; it < 4; it++) {
        int idx = it * 256 + tid;
        bool valid = idx < nk;
        unsigned bin = HBINS + lane;                 // unique sentinel
        if (valid) bin = fflip(g_key[start + idx]) >> 19;
        unsigned m = __match_any_sync(0xffffffffu, bin);
        int leader = __ffs(m) - 1;
        if (valid && lane == leader) atomicAdd(&h[bin], __popc(m));
    }
    __syncthreads();
    unsigned* H = g_hist + lvl * HBINS;
    for (int i = tid; i < HBINS; i += 256) {
        unsigned v = h[i];
        if (v) atomicAdd(&H[i], v);
    }
}

// ---------------- 2b. pivot bin per level (5 blocks) -----------------------
__global__ void pivotKernel() {
    int lvl = blockIdx.x, tid = threadIdx.x;
    __shared__ unsigned coarse[256];
    const unsigned* H = g_hist + lvl * HBINS;
    unsigned s = 0;
    for (int j = 0; j < 32; j++) s += H[tid * 32 + j];
    coarse[tid] = s;
    __syncthreads();
    if (tid == 0) {
        unsigned k = (unsigned)c_K[lvl], acc = 0;
        int cb = 0;
        for (int c = 255; c >= 0; c--) {
            if (acc + coarse[c] >= k) { cb = c; break; }
            acc += coarse[c];
        }
        int b13 = cb * 32;
        for (int b = cb * 32 + 31; b >= cb * 32; b--) {
            unsigned hv = H[b];
            if (acc + hv >= k) { b13 = b; break; }
            acc += hv;
        }
        g_b13[lvl]   = (unsigned)b13;
        g_need[lvl]  = (int)(k - acc);
        g_cg[lvl]    = 0;
        g_cntTie[lvl] = 0;
    }
}

// ---------------- common: write one selected candidate ---------------------
__device__ __forceinline__ void writeSel(int slot, float kf, int gidx, int lvl, int i,
                                         const float* __restrict__ reg,
                                         float l0, float l1, float l2, float l3) {
    g_selKey[slot] = kf;
    g_selCls[slot] = g_cls[gidx];
    g_selTie[slot] = (lvl << 17) | i;
    float b0 = reg[(size_t)i * 4 + 0], b1 = reg[(size_t)i * 4 + 1];
    float b2 = reg[(size_t)i * 4 + 2], b3 = reg[(size_t)i * 4 + 3];
    g_selBox[slot] = make_float4(fmaxf(b0, l0), fmaxf(b1, l1),
                                 fminf(b2, l2), fminf(b3, l3));
}

// ---------------- 2c. fill winners + tie buffer (86 blocks) ----------------
__global__ void fillKernel(const float* __restrict__ r0, const float* __restrict__ r1,
                           const float* __restrict__ r2, const float* __restrict__ r3,
                           const float* __restrict__ r4, const float* __restrict__ loc) {
    int lvl, start, nk; blk2lvl(blockIdx.x, lvl, start, nk);
    unsigned b13 = g_b13[lvl];
    int off = c_OFF[lvl], sbase = c_SOFF[lvl];
    const float* reg = (lvl == 0) ? r0 : (lvl == 1) ? r1 : (lvl == 2) ? r2 : (lvl == 3) ? r3 : r4;
    float l0 = loc[0], l1 = loc[1], l2 = loc[2], l3 = loc[3];
    int tid = threadIdx.x, lane = tid & 31;
    for (int it = 0; it < 4; it++) {
        int idx = it * 256 + tid;
        bool valid = idx < nk;
        float kf = 0.f; unsigned u = 0u, top = 0u;
        if (valid) { kf = g_key[start + idx]; u = fflip(kf); top = u >> 19; }
        bool win = valid && (top > b13);
        bool tie = valid && (top == b13);
        unsigned wb = __ballot_sync(0xffffffffu, win);
        if (wb) {
            int ld = __ffs(wb) - 1; int base = 0;
            if (lane == ld) base = atomicAdd(&g_cg[lvl], __popc(wb));
            base = __shfl_sync(0xffffffffu, base, ld);
            if (win) {
                int slot = sbase + base + __popc(wb & ((1u << lane) - 1u));
                writeSel(slot, kf, start + idx, lvl, start + idx - off, reg, l0, l1, l2, l3);
            }
        }
        unsigned tb = __ballot_sync(0xffffffffu, tie);
        if (tb) {
            int ld = __ffs(tb) - 1; int base = 0;
            if (lane == ld) base = atomicAdd(&g_cntTie[lvl], __popc(tb));
            base = __shfl_sync(0xffffffffu, base, ld);
            if (tie) {
                int t = base + __popc(tb & ((1u << lane) - 1u));
                g_bufA[off + t] = ((unsigned long long)u << 32) | (unsigned)(start + idx - off);
            }
        }
    }
}

// ---------------- 2d. refine tie buffer, finish selection (5 blocks) -------
__global__ void refineKernel(const float* __restrict__ r0, const float* __restrict__ r1,
                             const float* __restrict__ r2, const float* __restrict__ r3,
                             const float* __restrict__ r4, const float* __restrict__ loc) {
    int lvl = blockIdx.x, tid = threadIdx.x, hgrp = (tid >> 5) & 3;
    int off = c_OFF[lvl], sbase = c_SOFF[lvl];
    const float* reg = (lvl == 0) ? r0 : (lvl == 1) ? r1 : (lvl == 2) ? r2 : (lvl == 3) ? r3 : r4;
    float l0 = loc[0], l1 = loc[1], l2 = loc[2], l3 = loc[3];
    __shared__ unsigned hist[4][256];
    __shared__ int sNeed, cntIn, cntOut, sBsel;
    __shared__ int eqIdx[EQCAP];
    if (tid == 0) { sNeed = g_need[lvl]; cntIn = g_cntTie[lvl]; }
    __syncthreads();
    unsigned long long* bin  = g_bufA + off;
    unsigned long long* bout = g_bufB + off;
    const int SH[3] = {11, 3, 0};
    const unsigned MS[3] = {255u, 255u, 7u};
    for (int rr = 0; rr < 3; rr++) {
        int sh = SH[rr]; unsigned msk = MS[rr];
        for (int i2 = tid; i2 < 1024; i2 += 256) hist[i2 >> 8][i2 & 255] = 0u;
        if (tid == 0) cntOut = 0;
        __syncthreads();
        int m = cntIn;
        int lane = tid & 31;
        for (int i2 = tid; i2 < m; i2 += 256) {
            unsigned u = (unsigned)(bin[i2] >> 32);
            unsigned bb = (u >> sh) & msk;
            unsigned mm = __match_any_sync(__activemask(), bb);
            int ld = __ffs(mm) - 1;
            if (lane == ld) atomicAdd(&hist[hgrp][bb], __popc(mm));
        }
        __syncthreads();
        if (tid == 0) {
            int needv = sNeed; unsigned acc = 0; int b = 0;
            for (int bb2 = (int)msk; bb2 >= 0; bb2--) {
                unsigned hh = hist[0][bb2] + hist[1][bb2] + hist[2][bb2] + hist[3][bb2];
                if (acc + hh >= (unsigned)needv) { b = bb2; break; }
                acc += hh;
            }
            sNeed = needv - (int)acc;
            sBsel = b;
        }
        __syncthreads();
        unsigned bsel = (unsigned)sBsel;
        for (int i2 = tid; i2 < m; i2 += 256) {
            unsigned long long e = bin[i2];
            unsigned u = (unsigned)(e >> 32);
            unsigned by = (u >> sh) & msk;
            if (by > bsel) {
                int i = (int)(e & 0xFFFFFFFFull);
                int slot = sbase + atomicAdd(&g_cg[lvl], 1);
                writeSel(slot, g_key[off + i], off + i, lvl, i, reg, l0, l1, l2, l3);
            } else if (by == bsel) {
                int t = atomicAdd(&cntOut, 1);
                bout[t] = e;
            }
        }
        __syncthreads();
        if (tid == 0) cntIn = cntOut;
        unsigned long long* tp = bin; bin = bout; bout = tp;
        __syncthreads();
    }
    int ceF = cntIn; if (ceF > EQCAP) ceF = EQCAP;
    int needF = sNeed;
    for (int i2 = tid; i2 < ceF; i2 += 256) eqIdx[i2] = (int)(bin[i2] & 0xFFFFFFFFull);
    __syncthreads();
    if (needF < ceF && tid == 0) {
        // partial selection sort: needF smallest anchor indices first
        for (int t = 0; t < needF; t++) {
            int best = t;
            for (int q = t + 1; q < ceF; q++)
                if (eqIdx[q] < eqIdx[best]) best = q;
            int tmp = eqIdx[t]; eqIdx[t] = eqIdx[best]; eqIdx[best] = tmp;
        }
    }
    __syncthreads();
    int G = g_cg[lvl];                 // all winner atomics from this block done
    for (int t = tid; t < needF; t += 256) {
        int i = eqIdx[t];
        writeSel(sbase + G + t, g_key[off + i], off + i, lvl, i, reg, l0, l1, l2, l3);
    }
}

// ---------------- 3. rank-sort, 2 threads per element ----------------------
__global__ void rankKernel() {
    __shared__ unsigned long long sk[SEL_TOT];
    __shared__ int part[256];
    int tid = threadIdx.x;
    for (int i = tid; i < SEL_TOT; i += 256) {
        float kf = g_selKey[i];
        float ss = (kf > 0.0f) ? kf : 0.0f;
        unsigned tie = (unsigned)g_selTie[i];
        sk[i] = ((unsigned long long)fflip(ss) << 20) |
                (unsigned long long)(0xFFFFFu - tie);
    }
    __syncthreads();
    int e = blockIdx.x * 128 + (tid & 127);
    int half = tid >> 7;
    int cnt = 0;
    if (e < SEL_TOT) {
        unsigned long long mine = sk[e];
        int lo = half * 2128, hi = lo + 2128;
        #pragma unroll 8
        for (int i = lo; i < hi; i++) cnt += (sk[i] > mine) ? 1 : 0;
    }
    part[tid] = cnt;
    __syncthreads();
    if (half == 0 && e < SEL_TOT) {
        int rank = part[tid] + part[tid + 128];
        float kf = g_selKey[e];
        g_srtScore[rank] = (kf > 0.0f) ? kf : 0.0f;
        g_srtValid[rank] = (kf > 0.0f) ? 1 : 0;
        g_srtCls[rank]   = g_selCls[e];
        g_srtBox[rank]   = g_selBox[e];
    }
    if (blockIdx.x == 0 && tid < 16) g_changeArr[tid] = 0u;
}

// ------- 4. suppression bitmask, column-major (bit k of word w, col j) ------
__global__ void matrixKernel() {
    int jbase = blockIdx.x * 128;
    int kbase = blockIdx.y * KSLAB;
    if (kbase >= jbase + 128) return;
    __shared__ float4 kb[KSLAB];
    __shared__ float  ka[KSLAB];
    int tid = threadIdx.x;
    for (int t = tid; t < KSLAB; t += 128) {
        int kk = kbase + t;
        float4 b = (kk < SEL_TOT) ? g_srtBox[kk] : make_float4(0.f, 0.f, 0.f, 0.f);
        kb[t] = b;
        ka[t] = fmaxf(b.z - b.x, 0.f) * fmaxf(b.w - b.y, 0.f);
    }
    __syncthreads();
    int j = jbase + tid;
    if (j >= SEL_TOT) return;
    float4 bj = g_srtBox[j];
    float aj = fmaxf(bj.z - bj.x, 0.f) * fmaxf(bj.w - bj.y, 0.f);
    int w0 = kbase >> 5;
    for (int wi = 0; wi < KSLAB / 32; wi++) {
        unsigned word = 0u;
        int tb = wi * 32;
        if (kbase + tb < j) {
            #pragma unroll
            for (int t = 0; t < 32; t++) {
                int k = kbase + tb + t;
                float4 bk = kb[tb + t];
                float iy1 = fmaxf(bk.x, bj.x), ix1 = fmaxf(bk.y, bj.y);
                float iy2 = fminf(bk.z, bj.z), ix2 = fminf(bk.w, bj.w);
                float inter = fmaxf(iy2 - iy1, 0.f) * fmaxf(ix2 - ix1, 0.f);
                float uni = aj + ka[tb + t] - inter;
                bool bit = (k < j) && (inter > 0.5f * fmaxf(uni, 1e-9f));
                if (bit) word |= (1u << t);
            }
        }
        g_Mt[(size_t)(w0 + wi) * SEL_PAD2 + j] = word;
    }
}

// -------- 5. all 16 Jacobi iterations in ONE kernel (grid barrier) ---------
__device__ __forceinline__ void gridBarrier(unsigned nb) {
    __threadfence();
    __syncthreads();
    if (threadIdx.x == 0) {
        unsigned my = atomicAdd(&g_barGen, 0u);
        if (atomicAdd(&g_barCount, 1u) == nb - 1u) {
            atomicExch(&g_barCount, 0u);
            __threadfence();
            atomicAdd(&g_barGen, 1u);
        } else {
            while (atomicAdd(&g_barGen, 0u) == my) __nanosleep(64);
        }
    }
    __syncthreads();
}

__global__ void nmsKernel() {
    __shared__ unsigned sK[WW];
    int tid = threadIdx.x;
    int j = blockIdx.x * 128 + tid;
    int lane = tid & 31;
    int wj = j >> 5;
    int wtop = (j > 0 && j < SEL_TOT) ? (((j - 1) >> 5) + 1) : 0;
    const unsigned* col = g_Mt + j;
    unsigned lastBal = 0xFFFFFFFFu;

    for (int t = 0; t < 16; t++) {
        if (t == 0) {
            for (int w = tid; w < WW; w += 128) sK[w] = 0xFFFFFFFFu;
        } else {
            const unsigned* src = g_keep[(t - 1) & 1];
            for (int w = tid; w < WW; w += 128) sK[w] = __ldcg(&src[w]);
        }
        __syncthreads();
        unsigned acc = 0u;
        #pragma unroll 4
        for (int w = 0; w < wtop; w++)
            acc |= col[(size_t)w * SEL_PAD2] & sK[w];
        bool keepNew = (acc == 0u);
        unsigned bal = __ballot_sync(0xffffffffu, keepNew);
        unsigned oldw = sK[wj];
        if (lane == 0) {
            __stcg(&g_keep[t & 1][wj], bal);
            if (bal != oldw) atomicOr(&g_changeArr[t], 1u);
        }
        lastBal = bal;
        gridBarrier(JTILES);
        unsigned chg = __ldcg(&g_changeArr[t]);
        __syncthreads();
        if (chg == 0u) break;
    }
    if (lane == 0) __stcg(&g_keepOut[wj], lastBal);
}

// ------------- 6. final top-100 via parallel bitmask compaction ------------
__global__ void finalKernel(float* __restrict__ out, const float* __restrict__ loc,
                            int out_size) {
    __shared__ unsigned kw[WW];
    __shared__ int wpfx[WW + 1];
    __shared__ int sel[100];
    __shared__ int sKtot;
    int tid = threadIdx.x;

    for (int w = tid; w < WW; w += blockDim.x) {
        unsigned vb = 0u;
        int base = w * 32;
        #pragma unroll 4
        for (int b = 0; b < 32; b++) {
            int j = base + b;
            if (j < SEL_TOT && g_srtValid[j]) vb |= (1u << b);
        }
        kw[w] = g_keepOut[w] & vb;
    }
    __syncthreads();
    if (tid == 0) {
        int acc = 0;
        for (int w = 0; w < WW; w++) { wpfx[w] = acc; acc += __popc(kw[w]); }
        wpfx[WW] = acc;
        sKtot = acc;
    }
    __syncthreads();
    int Ktot = sKtot;
    for (int j = tid; j < SEL_TOT; j += blockDim.x) {
        int w = j >> 5, b = j & 31;
        unsigned below = (b == 0) ? 0u : (kw[w] & (0xFFFFFFFFu >> (32 - b)));
        int kr = wpfx[w] + __popc(below);
        bool kp = (kw[w] >> b) & 1u;
        if (kp) {
            if (kr < 100) sel[kr] = j;
        } else if (Ktot < 100) {
            int pos = Ktot + (j - kr);
            if (pos < 100) sel[pos] = j;
        }
    }
    __syncthreads();
    if (tid < 100) {
        int j = sel[tid];
        int w = j >> 5, b = j & 31;
        bool kp = (kw[w] >> b) & 1u;
        float vy1 = loc[0], vx1 = loc[1], vy2 = loc[2], vx2 = loc[3];
        float oh = loc[4], ow = loc[5];
        float sy = oh / fmaxf(vy2 - vy1, 1e-6f);
        float sx = ow / fmaxf(vx2 - vx1, 1e-6f);
        float4 bx = g_srtBox[j];
        if (tid * 4 + 3 < out_size) {
            out[tid * 4 + 0] = (bx.x - vy1) * sy;
            out[tid * 4 + 1] = (bx.y - vx1) * sx;
            out[tid * 4 + 2] = (bx.z - vy1) * sy;
            out[tid * 4 + 3] = (bx.w - vx1) * sx;
        }
        if (400 + tid < out_size) out[400 + tid] = (float)g_srtCls[j];
        if (500 + tid < out_size) out[500 + tid] = kp ? g_srtScore[j] : 0.0f;
    }
}

// ---------------- host launcher --------------------------------------------
extern "C" void kernel_launch(void* const* d_in, const int* in_sizes, int n_in,
                              void* d_out, int out_size) {
    const float *cls[5] = {0, 0, 0, 0, 0};
    const float *reg[5] = {0, 0, 0, 0, 0};
    const float *loc = 0;
    for (int i = 0; i < n_in; i++) {
        switch (in_sizes[i]) {
            case 5242880: cls[0] = (const float*)d_in[i]; break;
            case 1310720: cls[1] = (const float*)d_in[i]; break;
            case 327680:  cls[2] = (const float*)d_in[i]; break;
            case 81920:   cls[3] = (const float*)d_in[i]; break;
            case 20480:   cls[4] = (const float*)d_in[i]; break;
            case 262144:  reg[0] = (const float*)d_in[i]; break;
            case 65536:   reg[1] = (const float*)d_in[i]; break;
            case 16384:   reg[2] = (const float*)d_in[i]; break;
            case 4096:    reg[3] = (const float*)d_in[i]; break;
            case 1024:    reg[4] = (const float*)d_in[i]; break;
            case 6:       loc    = (const float*)d_in[i]; break;
            default: break;
        }
    }
    int blocks = (N_TOT * 32 + 255) / 256;
    scoreKernel<<<blocks, 256>>>(cls[0], cls[1], cls[2], cls[3], cls[4]);
    histKernel<<<86, 256>>>();
    pivotKernel<<<5, 256>>>();
    fillKernel<<<86, 256>>>(reg[0], reg[1], reg[2], reg[3], reg[4], loc);
    refineKernel<<<5, 256>>>(reg[0], reg[1], reg[2], reg[3], reg[4], loc);
    rankKernel<<<JTILES, 256>>>();
    dim3 mg(JTILES, NSLAB);
    matrixKernel<<<mg, 128>>>();
    nmsKernel<<<JTILES, 128>>>();
    finalKernel<<<1, 256>>>((float*)d_out, loc, out_size);
}

// round 7
// speedup vs baseline: 1.4898x; 1.0292x over previous
#include <cuda_runtime.h>
#include <math.h>

#define N_TOT    87296
#define SEL_TOT  4256
#define SEL_PAD  4352
#define SEL_PAD2 4352
#define WW       136
#define JTILES   34
#define KSLAB    256
#define NSLAB    17
#define EQCAP    2048
#define HBINS    8192
#define MPITCH   137

// ---------------- scratch (device globals; no allocations) -----------------
__device__ float    g_key[N_TOT];
__device__ int      g_cls[N_TOT];
__device__ float    g_selKey[SEL_TOT];
__device__ int      g_selCls[SEL_TOT];
__device__ int      g_selTie[SEL_TOT];
__device__ float4   g_selBox[SEL_TOT];
__device__ float    g_srtScore[SEL_PAD];
__device__ int      g_srtCls[SEL_PAD];
__device__ int      g_srtValid[SEL_PAD];
__device__ float4   g_srtBox[SEL_PAD];
__device__ unsigned long long g_bufA[N_TOT];
__device__ unsigned long long g_bufB[N_TOT];
__device__ unsigned g_hist[5 * HBINS];          // zeroed at end of finalKernel
__device__ unsigned g_b13[5];
__device__ int      g_need[5];
__device__ int      g_cg[5];
__device__ int      g_cntTie[5];
__device__ unsigned g_Mt[(size_t)WW * SEL_PAD2]; // column-major: Mt[w][j]
__device__ unsigned g_keep[2][WW];
__device__ unsigned g_keepOut[WW];
__device__ unsigned g_changeArr[16];
__device__ unsigned g_barCount = 0;
__device__ unsigned g_barGen   = 0;             // monotonic across replays

__device__ __forceinline__ unsigned fflip(float f) {
    unsigned u = __float_as_uint(f);
    return (u & 0x80000000u) ? ~u : (u | 0x80000000u);
}

__constant__ int c_OFF[5]  = {0, 65536, 81920, 86016, 87040};
__constant__ int c_SOFF[5] = {0, 1000, 2000, 3000, 4000};
__constant__ int c_K[5]    = {1000, 1000, 1000, 1000, 256};

// ------- 1. per-anchor class max + fused histogram (warp per anchor) -------
__global__ void scoreKernel(const float* __restrict__ c0, const float* __restrict__ c1,
                            const float* __restrict__ c2, const float* __restrict__ c3,
                            const float* __restrict__ c4) {
    int warp = (blockIdx.x * blockDim.x + threadIdx.x) >> 5;
    int lane = threadIdx.x & 31;
    if (warp >= N_TOT) return;
    int off, lvl;
    const float* base;
    if      (warp < 65536) { off = 0;     base = c0; lvl = 0; }
    else if (warp < 81920) { off = 65536; base = c1; lvl = 1; }
    else if (warp < 86016) { off = 81920; base = c2; lvl = 2; }
    else if (warp < 87040) { off = 86016; base = c3; lvl = 3; }
    else                   { off = 87040; base = c4; lvl = 4; }
    int a = warp - off;
    float v = -1e30f; int bi = 1 << 20;
    if (lane < 20) {
        const float4* p4 = reinterpret_cast<const float4*>(base + (size_t)a * 80);
        float4 q = p4[lane];
        int cb = lane * 4;
        v = q.x; bi = cb;
        if (q.y > v) { v = q.y; bi = cb + 1; }
        if (q.z > v) { v = q.z; bi = cb + 2; }
        if (q.w > v) { v = q.w; bi = cb + 3; }
    }
    for (int o = 16; o; o >>= 1) {
        float ov = __shfl_down_sync(0xffffffffu, v, o);
        int   oi = __shfl_down_sync(0xffffffffu, bi, o);
        if (ov > v || (ov == v && oi < bi)) { v = ov; bi = oi; }
    }
    if (lane == 0) {
        float ps = 1.0f / (1.0f + expf(-v));
        float kf = (ps > 0.05f) ? ps : -1.0f;
        g_key[warp] = kf;
        g_cls[warp] = bi + 1;
        atomicAdd(&g_hist[lvl * HBINS + (fflip(kf) >> 19)], 1u);  // RED, no return
    }
}

// ---------------- 2a. pivot bin per level (5 blocks) -----------------------
__global__ void pivotKernel() {
    int lvl = blockIdx.x, tid = threadIdx.x;
    __shared__ unsigned coarse[256];
    const unsigned* H = g_hist + lvl * HBINS;
    unsigned s = 0;
    for (int j = 0; j < 32; j++) s += H[tid * 32 + j];
    coarse[tid] = s;
    __syncthreads();
    if (tid == 0) {
        unsigned k = (unsigned)c_K[lvl], acc = 0;
        int cb = 0;
        for (int c = 255; c >= 0; c--) {
            if (acc + coarse[c] >= k) { cb = c; break; }
            acc += coarse[c];
        }
        int b13 = cb * 32;
        for (int b = cb * 32 + 31; b >= cb * 32; b--) {
            unsigned hv = H[b];
            if (acc + hv >= k) { b13 = b; break; }
            acc += hv;
        }
        g_b13[lvl]    = (unsigned)b13;
        g_need[lvl]   = (int)(k - acc);
        g_cg[lvl]     = 0;
        g_cntTie[lvl] = 0;
    }
}

// ---------------- common: write one selected candidate ---------------------
__device__ __forceinline__ void writeSel(int slot, float kf, int gidx, int lvl, int i,
                                         const float* __restrict__ reg,
                                         float l0, float l1, float l2, float l3) {
    g_selKey[slot] = kf;
    g_selCls[slot] = g_cls[gidx];
    g_selTie[slot] = (lvl << 17) | i;
    float b0 = reg[(size_t)i * 4 + 0], b1 = reg[(size_t)i * 4 + 1];
    float b2 = reg[(size_t)i * 4 + 2], b3 = reg[(size_t)i * 4 + 3];
    g_selBox[slot] = make_float4(fmaxf(b0, l0), fmaxf(b1, l1),
                                 fminf(b2, l2), fminf(b3, l3));
}

// ---------------- 2b. fill winners + tie buffer (341 blocks) ---------------
__global__ void fillKernel(const float* __restrict__ r0, const float* __restrict__ r1,
                           const float* __restrict__ r2, const float* __restrict__ r3,
                           const float* __restrict__ r4, const float* __restrict__ loc) {
    int b = blockIdx.x, lvl, start;
    if      (b < 256) { lvl = 0; start = b * 256; }
    else if (b < 320) { lvl = 1; start = 65536 + (b - 256) * 256; }
    else if (b < 336) { lvl = 2; start = 81920 + (b - 320) * 256; }
    else if (b < 340) { lvl = 3; start = 86016 + (b - 336) * 256; }
    else              { lvl = 4; start = 87040; }
    unsigned b13 = g_b13[lvl];
    int off = c_OFF[lvl], sbase = c_SOFF[lvl];
    const float* reg = (lvl == 0) ? r0 : (lvl == 1) ? r1 : (lvl == 2) ? r2 : (lvl == 3) ? r3 : r4;
    float l0 = loc[0], l1 = loc[1], l2 = loc[2], l3 = loc[3];
    int tid = threadIdx.x, lane = tid & 31;
    int idx = start + tid;
    float kf = g_key[idx];
    unsigned u = fflip(kf);
    unsigned top = u >> 19;
    bool win = top > b13;
    bool tie = top == b13;
    unsigned wb = __ballot_sync(0xffffffffu, win);
    if (wb) {
        int ld = __ffs(wb) - 1; int bs = 0;
        if (lane == ld) bs = atomicAdd(&g_cg[lvl], __popc(wb));
        bs = __shfl_sync(0xffffffffu, bs, ld);
        if (win) {
            int slot = sbase + bs + __popc(wb & ((1u << lane) - 1u));
            writeSel(slot, kf, idx, lvl, idx - off, reg, l0, l1, l2, l3);
        }
    }
    unsigned tb = __ballot_sync(0xffffffffu, tie);
    if (tb) {
        int ld = __ffs(tb) - 1; int bs = 0;
        if (lane == ld) bs = atomicAdd(&g_cntTie[lvl], __popc(tb));
        bs = __shfl_sync(0xffffffffu, bs, ld);
        if (tie) {
            int t = bs + __popc(tb & ((1u << lane) - 1u));
            g_bufA[off + t] = ((unsigned long long)u << 32) | (unsigned)(idx - off);
        }
    }
}

// ---------------- 2c. refine tie buffer, finish selection (5 blocks) -------
__global__ void refineKernel(const float* __restrict__ r0, const float* __restrict__ r1,
                             const float* __restrict__ r2, const float* __restrict__ r3,
                             const float* __restrict__ r4, const float* __restrict__ loc) {
    int lvl = blockIdx.x, tid = threadIdx.x, hgrp = (tid >> 5) & 3;
    int off = c_OFF[lvl], sbase = c_SOFF[lvl];
    const float* reg = (lvl == 0) ? r0 : (lvl == 1) ? r1 : (lvl == 2) ? r2 : (lvl == 3) ? r3 : r4;
    float l0 = loc[0], l1 = loc[1], l2 = loc[2], l3 = loc[3];
    __shared__ unsigned hist[4][256];
    __shared__ int sNeed, cntIn, cntOut, sBsel;
    __shared__ int eqIdx[EQCAP];
    if (tid == 0) { sNeed = g_need[lvl]; cntIn = g_cntTie[lvl]; }
    __syncthreads();
    unsigned long long* bin  = g_bufA + off;
    unsigned long long* bout = g_bufB + off;
    const int SH[3] = {11, 3, 0};
    const unsigned MS[3] = {255u, 255u, 7u};
    for (int rr = 0; rr < 3; rr++) {
        int sh = SH[rr]; unsigned msk = MS[rr];
        for (int i2 = tid; i2 < 1024; i2 += 256) hist[i2 >> 8][i2 & 255] = 0u;
        if (tid == 0) cntOut = 0;
        __syncthreads();
        int m = cntIn;
        int lane = tid & 31;
        for (int i2 = tid; i2 < m; i2 += 256) {
            unsigned u = (unsigned)(bin[i2] >> 32);
            unsigned bb = (u >> sh) & msk;
            unsigned mm = __match_any_sync(__activemask(), bb);
            int ld = __ffs(mm) - 1;
            if (lane == ld) atomicAdd(&hist[hgrp][bb], __popc(mm));
        }
        __syncthreads();
        if (tid == 0) {
            int needv = sNeed; unsigned acc = 0; int b = 0;
            for (int bb2 = (int)msk; bb2 >= 0; bb2--) {
                unsigned hh = hist[0][bb2] + hist[1][bb2] + hist[2][bb2] + hist[3][bb2];
                if (acc + hh >= (unsigned)needv) { b = bb2; break; }
                acc += hh;
            }
            sNeed = needv - (int)acc;
            sBsel = b;
        }
        __syncthreads();
        unsigned bsel = (unsigned)sBsel;
        for (int i2 = tid; i2 < m; i2 += 256) {
            unsigned long long e = bin[i2];
            unsigned u = (unsigned)(e >> 32);
            unsigned by = (u >> sh) & msk;
            if (by > bsel) {
                int i = (int)(e & 0xFFFFFFFFull);
                int slot = sbase + atomicAdd(&g_cg[lvl], 1);
                writeSel(slot, g_key[off + i], off + i, lvl, i, reg, l0, l1, l2, l3);
            } else if (by == bsel) {
                int t = atomicAdd(&cntOut, 1);
                bout[t] = e;
            }
        }
        __syncthreads();
        if (tid == 0) cntIn = cntOut;
        unsigned long long* tp = bin; bin = bout; bout = tp;
        __syncthreads();
    }
    int ceF = cntIn; if (ceF > EQCAP) ceF = EQCAP;
    int needF = sNeed;
    for (int i2 = tid; i2 < ceF; i2 += 256) eqIdx[i2] = (int)(bin[i2] & 0xFFFFFFFFull);
    __syncthreads();
    if (needF < ceF && tid == 0) {
        for (int t = 0; t < needF; t++) {
            int best = t;
            for (int q = t + 1; q < ceF; q++)
                if (eqIdx[q] < eqIdx[best]) best = q;
            int tmp = eqIdx[t]; eqIdx[t] = eqIdx[best]; eqIdx[best] = tmp;
        }
    }
    __syncthreads();
    int G = g_cg[lvl];
    for (int t = tid; t < needF; t += 256) {
        int i = eqIdx[t];
        writeSel(sbase + G + t, g_key[off + i], off + i, lvl, i, reg, l0, l1, l2, l3);
    }
}

// ---------------- 3. rank-sort, 4 threads per element ----------------------
__global__ void rankKernel() {
    __shared__ unsigned long long sk[SEL_TOT];
    __shared__ int part[512];
    int tid = threadIdx.x;
    for (int i = tid; i < SEL_TOT; i += 512) {
        float kf = g_selKey[i];
        float ss = (kf > 0.0f) ? kf : 0.0f;
        unsigned tie = (unsigned)g_selTie[i];
        sk[i] = ((unsigned long long)fflip(ss) << 20) |
                (unsigned long long)(0xFFFFFu - tie);
    }
    __syncthreads();
    int e = blockIdx.x * 128 + (tid & 127);
    int seg = tid >> 7;                       // 0..3, 1064 each
    int cnt = 0;
    if (e < SEL_TOT) {
        unsigned long long mine = sk[e];
        int lo = seg * 1064, hi = lo + 1064;
        #pragma unroll 8
        for (int i = lo; i < hi; i++) cnt += (sk[i] > mine) ? 1 : 0;
    }
    part[tid] = cnt;
    __syncthreads();
    if (seg == 0 && e < SEL_TOT) {
        int rank = part[tid] + part[tid + 128] + part[tid + 256] + part[tid + 384];
        float kf = g_selKey[e];
        g_srtScore[rank] = (kf > 0.0f) ? kf : 0.0f;
        g_srtValid[rank] = (kf > 0.0f) ? 1 : 0;
        g_srtCls[rank]   = g_selCls[e];
        g_srtBox[rank]   = g_selBox[e];
    }
    if (blockIdx.x == 0 && tid < 16) g_changeArr[tid] = 0u;
}

// ------- 4. suppression bitmask, column-major (bit k of word w, col j) ------
__global__ void matrixKernel() {
    int jbase = blockIdx.x * 128;
    int kbase = blockIdx.y * KSLAB;
    if (kbase >= jbase + 128) return;
    __shared__ float4 kb[KSLAB];
    __shared__ float  ka[KSLAB];
    int tid = threadIdx.x;
    for (int t = tid; t < KSLAB; t += 128) {
        int kk = kbase + t;
        float4 b = (kk < SEL_TOT) ? g_srtBox[kk] : make_float4(0.f, 0.f, 0.f, 0.f);
        kb[t] = b;
        ka[t] = fmaxf(b.z - b.x, 0.f) * fmaxf(b.w - b.y, 0.f);
    }
    __syncthreads();
    int j = jbase + tid;
    if (j >= SEL_TOT) return;
    float4 bj = g_srtBox[j];
    float aj = fmaxf(bj.z - bj.x, 0.f) * fmaxf(bj.w - bj.y, 0.f);
    int w0 = kbase >> 5;
    for (int wi = 0; wi < KSLAB / 32; wi++) {
        unsigned word = 0u;
        int tb = wi * 32;
        if (kbase + tb < j) {
            #pragma unroll
            for (int t = 0; t < 32; t++) {
                int k = kbase + tb + t;
                float4 bk = kb[tb + t];
                float iy1 = fmaxf(bk.x, bj.x), ix1 = fmaxf(bk.y, bj.y);
                float iy2 = fminf(bk.z, bj.z), ix2 = fminf(bk.w, bj.w);
                float inter = fmaxf(iy2 - iy1, 0.f) * fmaxf(ix2 - ix1, 0.f);
                float uni = aj + ka[tb + t] - inter;
                bool bit = (k < j) && (inter > 0.5f * fmaxf(uni, 1e-9f));
                if (bit) word |= (1u << t);
            }
        }
        g_Mt[(size_t)(w0 + wi) * SEL_PAD2 + j] = word;
    }
}

// -------- 5. all 16 Jacobi iterations, M cached in smem (grid barrier) -----
__device__ __forceinline__ void gridBarrier(unsigned nb) {
    __threadfence();
    __syncthreads();
    if (threadIdx.x == 0) {
        unsigned my = atomicAdd(&g_barGen, 0u);
        if (atomicAdd(&g_barCount, 1u) == nb - 1u) {
            atomicExch(&g_barCount, 0u);
            __threadfence();
            atomicAdd(&g_barGen, 1u);
        } else {
            while (atomicAdd(&g_barGen, 0u) == my) __nanosleep(64);
        }
    }
    __syncthreads();
}

extern __shared__ unsigned sMdyn[];              // 128 * MPITCH words
__global__ void nmsKernel() {
    __shared__ unsigned sK[WW];
    int tid = threadIdx.x;
    int j = blockIdx.x * 128 + tid;
    int lane = tid & 31;
    int wj = j >> 5;
    int wtop = (j > 0 && j < SEL_TOT) ? (((j - 1) >> 5) + 1) : 0;
    unsigned* mrow = sMdyn + tid * MPITCH;
    for (int w = 0; w < WW; w++)                  // coalesced across tid
        mrow[w] = g_Mt[(size_t)w * SEL_PAD2 + j];
    unsigned lastBal = 0xFFFFFFFFu;

    for (int t = 0; t < 16; t++) {
        if (t == 0) {
            for (int w = tid; w < WW; w += 128) sK[w] = 0xFFFFFFFFu;
        } else {
            const unsigned* src = g_keep[(t - 1) & 1];
            for (int w = tid; w < WW; w += 128) sK[w] = __ldcg(&src[w]);
        }
        __syncthreads();
        unsigned acc = 0u;
        #pragma unroll 4
        for (int w = 0; w < wtop; w++) acc |= mrow[w] & sK[w];
        bool keepNew = (acc == 0u);
        unsigned bal = __ballot_sync(0xffffffffu, keepNew);
        unsigned oldw = sK[wj];
        if (lane == 0) {
            __stcg(&g_keep[t & 1][wj], bal);
            if (bal != oldw) atomicOr(&g_changeArr[t], 1u);
        }
        lastBal = bal;
        gridBarrier(JTILES);
        unsigned chg = __ldcg(&g_changeArr[t]);
        __syncthreads();
        if (chg == 0u) break;
    }
    if (lane == 0) __stcg(&g_keepOut[wj], lastBal);
}

// ------------- 6. final top-100 + rescale + hist reset ---------------------
__global__ void finalKernel(float* __restrict__ out, const float* __restrict__ loc,
                            int out_size) {
    __shared__ unsigned kw[WW];
    __shared__ int wpfx[WW + 1];
    __shared__ int sel[100];
    __shared__ int sKtot;
    int tid = threadIdx.x;

    for (int w = tid; w < WW; w += blockDim.x) {
        unsigned vb = 0u;
        int base = w * 32;
        #pragma unroll 4
        for (int b = 0; b < 32; b++) {
            int j = base + b;
            if (j < SEL_TOT && g_srtValid[j]) vb |= (1u << b);
        }
        kw[w] = g_keepOut[w] & vb;
    }
    __syncthreads();
    if (tid == 0) {
        int acc = 0;
        for (int w = 0; w < WW; w++) { wpfx[w] = acc; acc += __popc(kw[w]); }
        wpfx[WW] = acc;
        sKtot = acc;
    }
    __syncthreads();
    int Ktot = sKtot;
    for (int j = tid; j < SEL_TOT; j += blockDim.x) {
        int w = j >> 5, b = j & 31;
        unsigned below = (b == 0) ? 0u : (kw[w] & (0xFFFFFFFFu >> (32 - b)));
        int kr = wpfx[w] + __popc(below);
        bool kp = (kw[w] >> b) & 1u;
        if (kp) {
            if (kr < 100) sel[kr] = j;
        } else if (Ktot < 100) {
            int pos = Ktot + (j - kr);
            if (pos < 100) sel[pos] = j;
        }
    }
    __syncthreads();
    if (tid < 100) {
        int j = sel[tid];
        int w = j >> 5, b = j & 31;
        bool kp = (kw[w] >> b) & 1u;
        float vy1 = loc[0], vx1 = loc[1], vy2 = loc[2], vx2 = loc[3];
        float oh = loc[4], ow = loc[5];
        float sy = oh / fmaxf(vy2 - vy1, 1e-6f);
        float sx = ow / fmaxf(vx2 - vx1, 1e-6f);
        float4 bx = g_srtBox[j];
        if (tid * 4 + 3 < out_size) {
            out[tid * 4 + 0] = (bx.x - vy1) * sy;
            out[tid * 4 + 1] = (bx.y - vx1) * sx;
            out[tid * 4 + 2] = (bx.z - vy1) * sy;
            out[tid * 4 + 3] = (bx.w - vx1) * sx;
        }
        if (400 + tid < out_size) out[400 + tid] = (float)g_srtCls[j];
        if (500 + tid < out_size) out[500 + tid] = kp ? g_srtScore[j] : 0.0f;
    }
    // reset histogram for the next execution (first exec relies on zero-init)
    for (int i = tid; i < 5 * HBINS; i += blockDim.x) g_hist[i] = 0u;
}

// ---------------- host launcher --------------------------------------------
extern "C" void kernel_launch(void* const* d_in, const int* in_sizes, int n_in,
                              void* d_out, int out_size) {
    const float *cls[5] = {0, 0, 0, 0, 0};
    const float *reg[5] = {0, 0, 0, 0, 0};
    const float *loc = 0;
    for (int i = 0; i < n_in; i++) {
        switch (in_sizes[i]) {
            case 5242880: cls[0] = (const float*)d_in[i]; break;
            case 1310720: cls[1] = (const float*)d_in[i]; break;
            case 327680:  cls[2] = (const float*)d_in[i]; break;
            case 81920:   cls[3] = (const float*)d_in[i]; break;
            case 20480:   cls[4] = (const float*)d_in[i]; break;
            case 262144:  reg[0] = (const float*)d_in[i]; break;
            case 65536:   reg[1] = (const float*)d_in[i]; break;
            case 16384:   reg[2] = (const float*)d_in[i]; break;
            case 4096:    reg[3] = (const float*)d_in[i]; break;
            case 1024:    reg[4] = (const float*)d_in[i]; break;
            case 6:       loc    = (const float*)d_in[i]; break;
            default: break;
        }
    }
    static int smemSet = 0;
    if (!smemSet) {
        cudaFuncSetAttribute(nmsKernel, cudaFuncAttributeMaxDynamicSharedMemorySize,
                             128 * MPITCH * 4);
        smemSet = 1;
    }
    int blocks = (N_TOT * 32 + 255) / 256;
    scoreKernel<<<blocks, 256>>>(cls[0], cls[1], cls[2], cls[3], cls[4]);
    pivotKernel<<<5, 256>>>();
    fillKernel<<<341, 256>>>(reg[0], reg[1], reg[2], reg[3], reg[4], loc);
    refineKernel<<<5, 256>>>(reg[0], reg[1], reg[2], reg[3], reg[4], loc);
    rankKernel<<<JTILES, 512>>>();
    dim3 mg(JTILES, NSLAB);
    matrixKernel<<<mg, 128>>>();
    nmsKernel<<<JTILES, 128, 128 * MPITCH * 4>>>();
    finalKernel<<<1, 256>>>((float*)d_out, loc, out_size);
}